// round 1
// baseline (speedup 1.0000x reference)
#include <cuda_runtime.h>
#include <math.h>

#define BATCH 4
#define QN    8192
#define DIM   256
#define NQ    (BATCH*QN)        // 32768
#define H0c   128
#define W0c   128
#define H1c   64
#define W1c   64
#define LPTS  16                // L*P
#define EPSV  1e-5f

// ---------------- scratch (static device arrays; no allocation allowed) ----
__device__ float  g_map0t[BATCH*H0c*W0c*DIM];   // (B,H,W,D)  67 MB
__device__ float  g_map1t[BATCH*H1c*W1c*DIM];   // (B,H,W,D)  16.7 MB
__device__ float  g_inner[(size_t)NQ*DIM];      // 33.5 MB
__device__ float  g_proj [(size_t)NQ*52];       // 6.8 MB
__device__ float4 g_params[(size_t)NQ*LPTS];    // x, y, attn_w, pad

// ---------------- 1) transpose (B,D,H,W) -> (B,H,W,D) ----------------------
__global__ void transpose_kernel(const float* __restrict__ src, int H, int W, int which)
{
    float* dst = which ? g_map1t : g_map0t;
    __shared__ float tile[32][33];
    int w0 = blockIdx.x * 32;          // W tile
    int d0 = blockIdx.y * 32;          // D tile
    int bh = blockIdx.z;
    int b  = bh / H;
    int h  = bh % H;
    int tx = threadIdx.x, ty = threadIdx.y;   // 32 x 8

    const float* s = src + (((size_t)b*DIM + d0)*H + h) * W + w0;
    #pragma unroll
    for (int r = 0; r < 4; r++) {
        tile[ty + 8*r][tx] = s[(size_t)(ty + 8*r) * H * W + tx];
    }
    __syncthreads();
    float* dbase = dst + (((size_t)b*H + h)*W + w0) * DIM + d0;
    #pragma unroll
    for (int r = 0; r < 4; r++) {
        dbase[(size_t)(ty + 8*r) * DIM + tx] = tile[tx][ty + 8*r];
    }
}

// ---------------- 2) projections: warp per query ----------------------------
// proj layout per query: [0:4) rd, [4:36) off, [36:52) attn logits
__global__ void proj_kernel(const float* __restrict__ q,
                            const float* __restrict__ Wrd,   const float* __restrict__ brd,
                            const float* __restrict__ Woff,  const float* __restrict__ boff,
                            const float* __restrict__ Wattn, const float* __restrict__ battn)
{
    int warp = (blockIdx.x * blockDim.x + threadIdx.x) >> 5;
    int lane = threadIdx.x & 31;
    if (warp >= NQ) return;

    const float* qr = q + (size_t)warp * DIM;
    float qv[8];
    #pragma unroll
    for (int i = 0; i < 8; i++) qv[i] = qr[lane + 32*i];

    float* out = g_proj + (size_t)warp * 52;

    #pragma unroll
    for (int j = 0; j < 4; j++) {
        float s = 0.f;
        #pragma unroll
        for (int i = 0; i < 8; i++) s = fmaf(qv[i], __ldg(&Wrd[(lane + 32*i)*4 + j]), s);
        #pragma unroll
        for (int o = 16; o; o >>= 1) s += __shfl_xor_sync(0xffffffffu, s, o);
        if (lane == 0) out[j] = s + __ldg(&brd[j]);
    }
    #pragma unroll 4
    for (int j = 0; j < 32; j++) {
        float s = 0.f;
        #pragma unroll
        for (int i = 0; i < 8; i++) s = fmaf(qv[i], __ldg(&Woff[(lane + 32*i)*32 + j]), s);
        #pragma unroll
        for (int o = 16; o; o >>= 1) s += __shfl_xor_sync(0xffffffffu, s, o);
        if (lane == 0) out[4 + j] = s + __ldg(&boff[j]);
    }
    #pragma unroll 4
    for (int j = 0; j < 16; j++) {
        float s = 0.f;
        #pragma unroll
        for (int i = 0; i < 8; i++) s = fmaf(qv[i], __ldg(&Wattn[(lane + 32*i)*16 + j]), s);
        #pragma unroll
        for (int o = 16; o; o >>= 1) s += __shfl_xor_sync(0xffffffffu, s, o);
        if (lane == 0) out[36 + j] = s + __ldg(&battn[j]);
    }
}

// ---------------- 3) prep: sigmoid/softmax/coords -> per-point params -------
__global__ void prep_kernel(const float* __restrict__ base_ref)
{
    int qi = blockIdx.x * blockDim.x + threadIdx.x;
    if (qi >= NQ) return;
    int b = qi >> 13;                // / QN
    const float* pr = g_proj + (size_t)qi * 52;

    // attn softmax over 16 logits
    float lg[16];
    float m = -1e30f;
    #pragma unroll
    for (int j = 0; j < 16; j++) { lg[j] = pr[36 + j]; m = fmaxf(m, lg[j]); }
    float sum = 0.f;
    #pragma unroll
    for (int j = 0; j < 16; j++) { lg[j] = expf(lg[j] - m); sum += lg[j]; }
    float inv = 1.f / sum;

    float4* pp = g_params + (size_t)qi * LPTS;
    const int Hs[2] = {H0c, H1c}, Ws[2] = {W0c, W1c};

    #pragma unroll
    for (int l = 0; l < 2; l++) {
        float bx = base_ref[b*4 + l*2 + 0];
        float by = base_ref[b*4 + l*2 + 1];
        bx = fminf(fmaxf(bx, EPSV), 1.f - EPSV);
        by = fminf(fmaxf(by, EPSV), 1.f - EPSV);
        float lbx = logf(bx / (1.f - bx));
        float lby = logf(by / (1.f - by));
        float refx = 1.f / (1.f + expf(-(lbx + pr[l*2 + 0])));
        float refy = 1.f / (1.f + expf(-(lby + pr[l*2 + 1])));
        float Wf = (float)Ws[l], Hf = (float)Hs[l];

        #pragma unroll
        for (int p = 0; p < 8; p++) {
            float ox = pr[4 + (l*8 + p)*2 + 0];
            float oy = pr[4 + (l*8 + p)*2 + 1];
            float lx = refx + ox / Wf;
            float ly = refy + oy / Hf;
            if (l == 1) ly = ly - floorf(ly);       // jnp.remainder(., 1.0)
            float x = lx * Wf - 0.5f;
            float y = ly * Hf - 0.5f;
            x = fminf(fmaxf(x, 0.f), Wf - 1.f);
            y = fminf(fmaxf(y, 0.f), Hf - 1.f);
            pp[l*8 + p] = make_float4(x, y, lg[l*8 + p] * inv, 0.f);
        }
    }
}

// ---------------- 4) sampling: 64-thread group per query, float4 channels --
__global__ void sample_kernel()
{
    int g  = threadIdx.x >> 6;           // 4 queries per 256-thread block
    int t  = threadIdx.x & 63;           // channel group: channels 4t..4t+3
    int qi = blockIdx.x * 4 + g;
    int b  = qi >> 13;

    const float4* pp = g_params + (size_t)qi * LPTS;
    const float* m0 = g_map0t + (size_t)b * (H0c*W0c*DIM);
    const float* m1 = g_map1t + (size_t)b * (H1c*W1c*DIM);

    float4 acc = make_float4(0.f, 0.f, 0.f, 0.f);

    #pragma unroll
    for (int p = 0; p < 16; p++) {
        float4 par = __ldg(&pp[p]);
        const float* mp = (p < 8) ? m0 : m1;
        const int Wl = (p < 8) ? W0c : W1c;
        const int Hl = (p < 8) ? H0c : H1c;

        float x = par.x, y = par.y, wt = par.z;
        int x0 = (int)x, y0 = (int)y;            // x,y >= 0 after clip
        float wx = x - (float)x0;
        float wy = y - (float)y0;
        int x1 = min(x0 + 1, Wl - 1);
        int y1 = min(y0 + 1, Hl - 1);

        const float4* r00 = (const float4*)(mp + (size_t)(y0*Wl + x0) * DIM) + t;
        const float4* r01 = (const float4*)(mp + (size_t)(y0*Wl + x1) * DIM) + t;
        const float4* r10 = (const float4*)(mp + (size_t)(y1*Wl + x0) * DIM) + t;
        const float4* r11 = (const float4*)(mp + (size_t)(y1*Wl + x1) * DIM) + t;
        float4 v00 = __ldg(r00);
        float4 v01 = __ldg(r01);
        float4 v10 = __ldg(r10);
        float4 v11 = __ldg(r11);

        float w00 = (1.f - wx) * (1.f - wy) * wt;
        float w01 = wx * (1.f - wy) * wt;
        float w10 = (1.f - wx) * wy * wt;
        float w11 = wx * wy * wt;

        acc.x = fmaf(w00, v00.x, fmaf(w01, v01.x, fmaf(w10, v10.x, fmaf(w11, v11.x, acc.x))));
        acc.y = fmaf(w00, v00.y, fmaf(w01, v01.y, fmaf(w10, v10.y, fmaf(w11, v11.y, acc.y))));
        acc.z = fmaf(w00, v00.z, fmaf(w01, v01.z, fmaf(w10, v10.z, fmaf(w11, v11.z, acc.z))));
        acc.w = fmaf(w00, v00.w, fmaf(w01, v01.w, fmaf(w10, v10.w, fmaf(w11, v11.w, acc.w))));
    }

    ((float4*)(g_inner + (size_t)qi * DIM))[t] = acc;
}

// ---------------- 5) SGEMM: out = g_inner @ Wout + bout ---------------------
// M=32768, N=256, K=256. BM=BN=128, BK=8, 8x8 per thread, 256 threads.
__global__ void gemm_kernel(const float* __restrict__ Wout,
                            const float* __restrict__ bout,
                            float* __restrict__ out)
{
    const int BM = 128, BN = 128, BK = 8;
    __shared__ __align__(16) float As[BK][BM];
    __shared__ __align__(16) float Bs[BK][BN];

    int bx = blockIdx.x;   // 0..1
    int by = blockIdx.y;   // 0..255
    int tid = threadIdx.x; // 256
    int tx = tid & 15;     // col group
    int ty = tid >> 4;     // row group

    const float* A = g_inner + (size_t)by * BM * 256;
    const float* Bp = Wout + bx * BN;
    float* C = out + (size_t)by * BM * 256 + bx * BN;

    int arow = tid >> 1,  acol = (tid & 1) * 4;   // A tile load: 128x8
    int brow = tid >> 5,  bcol = (tid & 31) * 4;  // B tile load: 8x128

    float acc[8][8];
    #pragma unroll
    for (int i = 0; i < 8; i++)
        #pragma unroll
        for (int j = 0; j < 8; j++) acc[i][j] = 0.f;

    for (int k0 = 0; k0 < 256; k0 += BK) {
        float4 a4 = *(const float4*)(A + (size_t)arow * 256 + k0 + acol);
        As[acol + 0][arow] = a4.x;
        As[acol + 1][arow] = a4.y;
        As[acol + 2][arow] = a4.z;
        As[acol + 3][arow] = a4.w;
        float4 b4 = *(const float4*)(Bp + (size_t)(k0 + brow) * 256 + bcol);
        *(float4*)&Bs[brow][bcol] = b4;
        __syncthreads();

        #pragma unroll
        for (int k = 0; k < BK; k++) {
            float4 ra0 = *(const float4*)&As[k][ty*8];
            float4 ra1 = *(const float4*)&As[k][ty*8 + 4];
            float4 rb0 = *(const float4*)&Bs[k][tx*8];
            float4 rb1 = *(const float4*)&Bs[k][tx*8 + 4];
            float ra[8] = {ra0.x, ra0.y, ra0.z, ra0.w, ra1.x, ra1.y, ra1.z, ra1.w};
            float rb[8] = {rb0.x, rb0.y, rb0.z, rb0.w, rb1.x, rb1.y, rb1.z, rb1.w};
            #pragma unroll
            for (int i = 0; i < 8; i++)
                #pragma unroll
                for (int j = 0; j < 8; j++)
                    acc[i][j] = fmaf(ra[i], rb[j], acc[i][j]);
        }
        __syncthreads();
    }

    #pragma unroll
    for (int i = 0; i < 8; i++) {
        #pragma unroll
        for (int j = 0; j < 8; j += 4) {
            int col = bx * BN + tx * 8 + j;
            float4 r;
            r.x = acc[i][j + 0] + __ldg(&bout[col + 0]);
            r.y = acc[i][j + 1] + __ldg(&bout[col + 1]);
            r.z = acc[i][j + 2] + __ldg(&bout[col + 2]);
            r.w = acc[i][j + 3] + __ldg(&bout[col + 3]);
            *(float4*)(C + (size_t)(ty * 8 + i) * 256 + tx * 8 + j) = r;
        }
    }
}

// ---------------- launch -----------------------------------------------------
extern "C" void kernel_launch(void* const* d_in, const int* in_sizes, int n_in,
                              void* d_out, int out_size)
{
    const float* q        = (const float*)d_in[0];
    const float* map0     = (const float*)d_in[1];
    const float* map1     = (const float*)d_in[2];
    const float* base_ref = (const float*)d_in[3];
    const float* Wrd      = (const float*)d_in[4];
    const float* brd      = (const float*)d_in[5];
    const float* Woff     = (const float*)d_in[6];
    const float* boff     = (const float*)d_in[7];
    const float* Wattn    = (const float*)d_in[8];
    const float* battn    = (const float*)d_in[9];
    const float* Wout     = (const float*)d_in[10];
    const float* bout     = (const float*)d_in[11];
    float* out = (float*)d_out;

    // 1) transpose maps to channel-last
    transpose_kernel<<<dim3(W0c/32, DIM/32, BATCH*H0c), dim3(32, 8)>>>(map0, H0c, W0c, 0);
    transpose_kernel<<<dim3(W1c/32, DIM/32, BATCH*H1c), dim3(32, 8)>>>(map1, H1c, W1c, 1);

    // 2) projections (warp per query)
    proj_kernel<<<NQ/8, 256>>>(q, Wrd, brd, Woff, boff, Wattn, battn);

    // 3) per-query point params
    prep_kernel<<<NQ/256, 256>>>(base_ref);

    // 4) sampling + attention-weighted accumulate
    sample_kernel<<<NQ/4, 256>>>();

    // 5) output projection
    gemm_kernel<<<dim3(2, NQ/128), 256>>>(Wout, bout, out);
}

// round 2
// speedup vs baseline: 3.7984x; 3.7984x over previous
#include <cuda_runtime.h>
#include <math.h>

#define BATCH 4
#define QN    8192
#define DIM   256
#define NQ    (BATCH*QN)        // 32768
#define H0c   128
#define W0c   128
#define H1c   64
#define W1c   64
#define LPTS  16                // L*P
#define NOUT  52                // 4 rd + 32 off + 16 attn
#define EPSV  1e-5f

// ---------------- scratch (static device arrays; no allocation allowed) ----
__device__ float  g_map0t[BATCH*H0c*W0c*DIM];   // (B,H,W,D)  67 MB
__device__ float  g_map1t[BATCH*H1c*W1c*DIM];   // (B,H,W,D)  16.7 MB
__device__ float  g_inner[(size_t)NQ*DIM];      // 33.5 MB
__device__ float4 g_params[(size_t)NQ*LPTS];    // x, y, attn_w, pad
__device__ float  g_Wt[NOUT*DIM];               // transposed fused weights (j-major)
__device__ float  g_bias[NOUT];

// ---------------- 0) weight prep: transpose into j-major layout -------------
__global__ void wprep_kernel(const float* __restrict__ Wrd,   const float* __restrict__ brd,
                             const float* __restrict__ Woff,  const float* __restrict__ boff,
                             const float* __restrict__ Wattn, const float* __restrict__ battn)
{
    int j = blockIdx.x;          // 0..51
    int d = threadIdx.x;         // 0..255
    float v;
    if (j < 4)        v = Wrd [d*4  + j];
    else if (j < 36)  v = Woff[d*32 + (j-4)];
    else              v = Wattn[d*16 + (j-36)];
    g_Wt[j*DIM + d] = v;
    if (d == 0) {
        float bv;
        if (j < 4)        bv = brd[j];
        else if (j < 36)  bv = boff[j-4];
        else              bv = battn[j-36];
        g_bias[j] = bv;
    }
}

// ---------------- 1) transpose (B,D,H,W) -> (B,H,W,D) ----------------------
__global__ void transpose_kernel(const float* __restrict__ src, int H, int W, int which)
{
    float* dst = which ? g_map1t : g_map0t;
    __shared__ float tile[32][33];
    int w0 = blockIdx.x * 32;          // W tile
    int d0 = blockIdx.y * 32;          // D tile
    int bh = blockIdx.z;
    int b  = bh / H;
    int h  = bh % H;
    int tx = threadIdx.x, ty = threadIdx.y;   // 32 x 8

    const float* s = src + (((size_t)b*DIM + d0)*H + h) * W + w0;
    #pragma unroll
    for (int r = 0; r < 4; r++) {
        tile[ty + 8*r][tx] = s[(size_t)(ty + 8*r) * H * W + tx];
    }
    __syncthreads();
    float* dbase = dst + (((size_t)b*H + h)*W + w0) * DIM + d0;
    #pragma unroll
    for (int r = 0; r < 4; r++) {
        dbase[(size_t)(ty + 8*r) * DIM + tx] = tile[tx][ty + 8*r];
    }
}

// ---------------- 2) fused projection + point-param prep --------------------
// One warp per query. Coalesced weight reads from g_Wt (j-major).
// Butterfly reduction leaves each dot product in ALL lanes, so lanes 0..15
// then each finalize one sampling point.
__global__ void proj_prep_kernel(const float* __restrict__ q,
                                 const float* __restrict__ base_ref)
{
    int warp = (blockIdx.x * blockDim.x + threadIdx.x) >> 5;
    int lane = threadIdx.x & 31;
    if (warp >= NQ) return;
    int b = warp >> 13;              // / QN

    const float* qr = q + (size_t)warp * DIM;
    float qv[8];
    #pragma unroll
    for (int i = 0; i < 8; i++) qv[i] = qr[lane + 32*i];

    float r[NOUT];
    #pragma unroll
    for (int j = 0; j < NOUT; j++) {
        const float* wj = g_Wt + j*DIM;
        float s = 0.f;
        #pragma unroll
        for (int i = 0; i < 8; i++) s = fmaf(qv[i], wj[lane + 32*i], s);
        #pragma unroll
        for (int o = 16; o; o >>= 1) s += __shfl_xor_sync(0xffffffffu, s, o);
        r[j] = s + g_bias[j];
    }

    if (lane < 16) {
        // softmax over attn logits r[36..51] (every lane has all values)
        float m = -1e30f;
        #pragma unroll
        for (int j = 0; j < 16; j++) m = fmaxf(m, r[36+j]);
        float sum = 0.f;
        #pragma unroll
        for (int j = 0; j < 16; j++) sum += expf(r[36+j] - m);
        float wt = expf(r[36+lane] - m) / sum;

        int p = lane;                // point 0..15
        int l = p >> 3;              // level
        float Wf = l ? (float)W1c : (float)W0c;
        float Hf = l ? (float)H1c : (float)H0c;

        float bx = base_ref[b*4 + l*2 + 0];
        float by = base_ref[b*4 + l*2 + 1];
        bx = fminf(fmaxf(bx, EPSV), 1.f - EPSV);
        by = fminf(fmaxf(by, EPSV), 1.f - EPSV);
        float lbx = logf(bx / (1.f - bx));
        float lby = logf(by / (1.f - by));
        float refx = 1.f / (1.f + expf(-(lbx + r[l*2 + 0])));
        float refy = 1.f / (1.f + expf(-(lby + r[l*2 + 1])));

        float ox = r[4 + p*2 + 0];
        float oy = r[4 + p*2 + 1];
        float lx = refx + ox / Wf;
        float ly = refy + oy / Hf;
        if (l == 1) ly = ly - floorf(ly);        // jnp.remainder(., 1.0)
        float x = lx * Wf - 0.5f;
        float y = ly * Hf - 0.5f;
        x = fminf(fmaxf(x, 0.f), Wf - 1.f);
        y = fminf(fmaxf(y, 0.f), Hf - 1.f);

        g_params[(size_t)warp*LPTS + p] = make_float4(x, y, wt, 0.f);
    }
}

// ---------------- 3) sampling: 64-thread group per query, float4 channels --
__global__ void sample_kernel()
{
    int g  = threadIdx.x >> 6;           // 4 queries per 256-thread block
    int t  = threadIdx.x & 63;           // channel group: channels 4t..4t+3
    int qi = blockIdx.x * 4 + g;
    int b  = qi >> 13;

    const float4* pp = g_params + (size_t)qi * LPTS;
    const float* m0 = g_map0t + (size_t)b * (H0c*W0c*DIM);
    const float* m1 = g_map1t + (size_t)b * (H1c*W1c*DIM);

    float4 acc = make_float4(0.f, 0.f, 0.f, 0.f);

    #pragma unroll
    for (int p = 0; p < 16; p++) {
        float4 par = __ldg(&pp[p]);
        const float* mp = (p < 8) ? m0 : m1;
        const int Wl = (p < 8) ? W0c : W1c;
        const int Hl = (p < 8) ? H0c : H1c;

        float x = par.x, y = par.y, wt = par.z;
        int x0 = (int)x, y0 = (int)y;            // x,y >= 0 after clip
        float wx = x - (float)x0;
        float wy = y - (float)y0;
        int x1 = min(x0 + 1, Wl - 1);
        int y1 = min(y0 + 1, Hl - 1);

        const float4* r00 = (const float4*)(mp + (size_t)(y0*Wl + x0) * DIM) + t;
        const float4* r01 = (const float4*)(mp + (size_t)(y0*Wl + x1) * DIM) + t;
        const float4* r10 = (const float4*)(mp + (size_t)(y1*Wl + x0) * DIM) + t;
        const float4* r11 = (const float4*)(mp + (size_t)(y1*Wl + x1) * DIM) + t;
        float4 v00 = __ldg(r00);
        float4 v01 = __ldg(r01);
        float4 v10 = __ldg(r10);
        float4 v11 = __ldg(r11);

        float w00 = (1.f - wx) * (1.f - wy) * wt;
        float w01 = wx * (1.f - wy) * wt;
        float w10 = (1.f - wx) * wy * wt;
        float w11 = wx * wy * wt;

        acc.x = fmaf(w00, v00.x, fmaf(w01, v01.x, fmaf(w10, v10.x, fmaf(w11, v11.x, acc.x))));
        acc.y = fmaf(w00, v00.y, fmaf(w01, v01.y, fmaf(w10, v10.y, fmaf(w11, v11.y, acc.y))));
        acc.z = fmaf(w00, v00.z, fmaf(w01, v01.z, fmaf(w10, v10.z, fmaf(w11, v11.z, acc.z))));
        acc.w = fmaf(w00, v00.w, fmaf(w01, v01.w, fmaf(w10, v10.w, fmaf(w11, v11.w, acc.w))));
    }

    ((float4*)(g_inner + (size_t)qi * DIM))[t] = acc;
}

// ---------------- 4) SGEMM: out = g_inner @ Wout + bout ---------------------
// M=32768, N=256, K=256. BM=BN=128, BK=8, 8x8 per thread, 256 threads.
__global__ void gemm_kernel(const float* __restrict__ Wout,
                            const float* __restrict__ bout,
                            float* __restrict__ out)
{
    const int BM = 128, BN = 128, BK = 8;
    __shared__ __align__(16) float As[BK][BM];
    __shared__ __align__(16) float Bs[BK][BN];

    int bx = blockIdx.x;   // 0..1
    int by = blockIdx.y;   // 0..255
    int tid = threadIdx.x; // 256
    int tx = tid & 15;     // col group
    int ty = tid >> 4;     // row group

    const float* A = g_inner + (size_t)by * BM * 256;
    const float* Bp = Wout + bx * BN;
    float* C = out + (size_t)by * BM * 256 + bx * BN;

    int arow = tid >> 1,  acol = (tid & 1) * 4;   // A tile load: 128x8
    int brow = tid >> 5,  bcol = (tid & 31) * 4;  // B tile load: 8x128

    float acc[8][8];
    #pragma unroll
    for (int i = 0; i < 8; i++)
        #pragma unroll
        for (int j = 0; j < 8; j++) acc[i][j] = 0.f;

    for (int k0 = 0; k0 < 256; k0 += BK) {
        float4 a4 = *(const float4*)(A + (size_t)arow * 256 + k0 + acol);
        As[acol + 0][arow] = a4.x;
        As[acol + 1][arow] = a4.y;
        As[acol + 2][arow] = a4.z;
        As[acol + 3][arow] = a4.w;
        float4 b4 = *(const float4*)(Bp + (size_t)(k0 + brow) * 256 + bcol);
        *(float4*)&Bs[brow][bcol] = b4;
        __syncthreads();

        #pragma unroll
        for (int k = 0; k < BK; k++) {
            float4 ra0 = *(const float4*)&As[k][ty*8];
            float4 ra1 = *(const float4*)&As[k][ty*8 + 4];
            float4 rb0 = *(const float4*)&Bs[k][tx*8];
            float4 rb1 = *(const float4*)&Bs[k][tx*8 + 4];
            float ra[8] = {ra0.x, ra0.y, ra0.z, ra0.w, ra1.x, ra1.y, ra1.z, ra1.w};
            float rb[8] = {rb0.x, rb0.y, rb0.z, rb0.w, rb1.x, rb1.y, rb1.z, rb1.w};
            #pragma unroll
            for (int i = 0; i < 8; i++)
                #pragma unroll
                for (int j = 0; j < 8; j++)
                    acc[i][j] = fmaf(ra[i], rb[j], acc[i][j]);
        }
        __syncthreads();
    }

    #pragma unroll
    for (int i = 0; i < 8; i++) {
        #pragma unroll
        for (int j = 0; j < 8; j += 4) {
            int col = bx * BN + tx * 8 + j;
            float4 r;
            r.x = acc[i][j + 0] + __ldg(&bout[col + 0]);
            r.y = acc[i][j + 1] + __ldg(&bout[col + 1]);
            r.z = acc[i][j + 2] + __ldg(&bout[col + 2]);
            r.w = acc[i][j + 3] + __ldg(&bout[col + 3]);
            *(float4*)(C + (size_t)(ty * 8 + i) * 256 + tx * 8 + j) = r;
        }
    }
}

// ---------------- launch -----------------------------------------------------
extern "C" void kernel_launch(void* const* d_in, const int* in_sizes, int n_in,
                              void* d_out, int out_size)
{
    const float* q        = (const float*)d_in[0];
    const float* map0     = (const float*)d_in[1];
    const float* map1     = (const float*)d_in[2];
    const float* base_ref = (const float*)d_in[3];
    const float* Wrd      = (const float*)d_in[4];
    const float* brd      = (const float*)d_in[5];
    const float* Woff     = (const float*)d_in[6];
    const float* boff     = (const float*)d_in[7];
    const float* Wattn    = (const float*)d_in[8];
    const float* battn    = (const float*)d_in[9];
    const float* Wout     = (const float*)d_in[10];
    const float* bout     = (const float*)d_in[11];
    float* out = (float*)d_out;

    // 0) weight layout prep (tiny)
    wprep_kernel<<<NOUT, 256>>>(Wrd, brd, Woff, boff, Wattn, battn);

    // 1) transpose maps to channel-last
    transpose_kernel<<<dim3(W0c/32, DIM/32, BATCH*H0c), dim3(32, 8)>>>(map0, H0c, W0c, 0);
    transpose_kernel<<<dim3(W1c/32, DIM/32, BATCH*H1c), dim3(32, 8)>>>(map1, H1c, W1c, 1);

    // 2) fused projections + per-point params (warp per query)
    proj_prep_kernel<<<NQ/8, 256>>>(q, base_ref);

    // 3) sampling + attention-weighted accumulate
    sample_kernel<<<NQ/4, 256>>>();

    // 4) output projection
    gemm_kernel<<<dim3(2, NQ/128), 256>>>(Wout, bout, out);
}